// round 1
// baseline (speedup 1.0000x reference)
#include <cuda_runtime.h>
#include <stdint.h>

// ---------------------------------------------------------------------------
// Threefry-2x32 (JAX flavor), 20 rounds.
// ---------------------------------------------------------------------------

#define TF_ROUND(x0, x1, r)                      \
    do {                                         \
        (x0) += (x1);                            \
        (x1) = __funnelshift_l((x1), (x1), (r)); \
        (x1) ^= (x0);                            \
    } while (0)

struct Keys {
    unsigned k0[5];
    unsigned k1[5];
};

// Device: full block with counter (hi=0, lo=ctr), returns x0 ^ x1 (the
// 32-bit "partitionable" random_bits fold).
__device__ __forceinline__ unsigned tf_fold(unsigned k0, unsigned k1, unsigned ctr)
{
    unsigned k2 = k0 ^ k1 ^ 0x1BD11BDAu;
    unsigned x0 = k0;        // hi counter (0) + k0
    unsigned x1 = ctr + k1;  // lo counter + k1

    TF_ROUND(x0, x1, 13); TF_ROUND(x0, x1, 15); TF_ROUND(x0, x1, 26); TF_ROUND(x0, x1, 6);
    x0 += k1; x1 += k2 + 1u;
    TF_ROUND(x0, x1, 17); TF_ROUND(x0, x1, 29); TF_ROUND(x0, x1, 16); TF_ROUND(x0, x1, 24);
    x0 += k2; x1 += k0 + 2u;
    TF_ROUND(x0, x1, 13); TF_ROUND(x0, x1, 15); TF_ROUND(x0, x1, 26); TF_ROUND(x0, x1, 6);
    x0 += k0; x1 += k1 + 3u;
    TF_ROUND(x0, x1, 17); TF_ROUND(x0, x1, 29); TF_ROUND(x0, x1, 16); TF_ROUND(x0, x1, 24);
    x0 += k1; x1 += k2 + 4u;
    TF_ROUND(x0, x1, 13); TF_ROUND(x0, x1, 15); TF_ROUND(x0, x1, 26); TF_ROUND(x0, x1, 6);
    x0 += k2; x1 += k0 + 5u;

    return x0 ^ x1;
}

// Host: full block, both outputs (needed for foldlike key split).
static void tf_block_host(unsigned k0, unsigned k1, unsigned c0, unsigned c1,
                          unsigned* o0, unsigned* o1)
{
    unsigned k2 = k0 ^ k1 ^ 0x1BD11BDAu;
    unsigned x0 = c0 + k0;
    unsigned x1 = c1 + k1;
    auto rotl = [](unsigned v, int r) -> unsigned {
        return (v << r) | (v >> (32 - r));
    };
#define TFH_ROUND(r) do { x0 += x1; x1 = rotl(x1, r); x1 ^= x0; } while (0)
    TFH_ROUND(13); TFH_ROUND(15); TFH_ROUND(26); TFH_ROUND(6);
    x0 += k1; x1 += k2 + 1u;
    TFH_ROUND(17); TFH_ROUND(29); TFH_ROUND(16); TFH_ROUND(24);
    x0 += k2; x1 += k0 + 2u;
    TFH_ROUND(13); TFH_ROUND(15); TFH_ROUND(26); TFH_ROUND(6);
    x0 += k0; x1 += k1 + 3u;
    TFH_ROUND(17); TFH_ROUND(29); TFH_ROUND(16); TFH_ROUND(24);
    x0 += k1; x1 += k2 + 4u;
    TFH_ROUND(13); TFH_ROUND(15); TFH_ROUND(26); TFH_ROUND(6);
    x0 += k2; x1 += k0 + 5u;
#undef TFH_ROUND
    *o0 = x0;
    *o1 = x1;
}

// ---------------------------------------------------------------------------
// Fused multisample-dropout + 3-wide affine head.
// x: [32, 2048, 1024] f32, W: [3, 1024] f32, b: [3] f32 -> out: [32, 2048, 3]
// One CTA per (b, s) row. 256 threads, 4 elements/thread (float4).
// ---------------------------------------------------------------------------

__global__ __launch_bounds__(256, 4)
void nbme_head_kernel(const float* __restrict__ x,
                      const float* __restrict__ W,
                      const float* __restrict__ bias,
                      float* __restrict__ out,
                      Keys kk)
{
    // Exact fp32 bernoulli thresholds for keep-prob q = 0.9, 0.8, 0.7, 0.6, 0.5:
    // keep  <=>  ((bits >> 9) < T)   (u = m / 2^23 < float32(q))
    const unsigned T[5] = {7549747u, 6710887u, 5872026u, 5033165u, 4194304u};
    const float    R[5] = {1.0f / 0.9f, 1.25f, 1.0f / 0.7f, 1.0f / 0.6f, 2.0f};

    const int row = blockIdx.x;          // 0 .. 65535
    const int t   = threadIdx.x;         // 0 .. 255
    const unsigned ibase = (unsigned)row * 1024u + 4u * (unsigned)t;

    const float4 xv  = *reinterpret_cast<const float4*>(x + (size_t)ibase);
    const float4 w0v = __ldg(reinterpret_cast<const float4*>(W + 4 * t));
    const float4 w1v = __ldg(reinterpret_cast<const float4*>(W + 1024 + 4 * t));
    const float4 w2v = __ldg(reinterpret_cast<const float4*>(W + 2048 + 4 * t));

    const float xa[4]  = {xv.x, xv.y, xv.z, xv.w};
    const float w0a[4] = {w0v.x, w0v.y, w0v.z, w0v.w};
    const float w1a[4] = {w1v.x, w1v.y, w1v.z, w1v.w};
    const float w2a[4] = {w2v.x, w2v.y, w2v.z, w2v.w};

    float s0 = 0.0f, s1 = 0.0f, s2 = 0.0f;

#pragma unroll
    for (int e = 0; e < 4; ++e) {
        const unsigned ctr = ibase + (unsigned)e;
        float coef = 0.0f;
#pragma unroll
        for (int j = 0; j < 5; ++j) {
            const unsigned m = tf_fold(kk.k0[j], kk.k1[j], ctr) >> 9;
            if (m < T[j]) coef += R[j];
        }
        const float y = xa[e] * (coef * 0.2f);
        s0 = fmaf(y, w0a[e], s0);
        s1 = fmaf(y, w1a[e], s1);
        s2 = fmaf(y, w2a[e], s2);
    }

    // Warp butterfly reduction.
#pragma unroll
    for (int off = 16; off > 0; off >>= 1) {
        s0 += __shfl_xor_sync(0xFFFFFFFFu, s0, off);
        s1 += __shfl_xor_sync(0xFFFFFFFFu, s1, off);
        s2 += __shfl_xor_sync(0xFFFFFFFFu, s2, off);
    }

    __shared__ float red[3][8];
    const int warp = t >> 5;
    const int lane = t & 31;
    if (lane == 0) {
        red[0][warp] = s0;
        red[1][warp] = s1;
        red[2][warp] = s2;
    }
    __syncthreads();

    if (t < 3) {
        float s = 0.0f;
#pragma unroll
        for (int w = 0; w < 8; ++w) s += red[t][w];
        out[(size_t)row * 3 + t] = s + __ldg(bias + t);
    }
}

// ---------------------------------------------------------------------------
// Launch
// ---------------------------------------------------------------------------

extern "C" void kernel_launch(void* const* d_in, const int* in_sizes, int n_in,
                              void* d_out, int out_size)
{
    (void)in_sizes; (void)n_in; (void)out_size;

    const float* x  = (const float*)d_in[0];  // [32, 2048, 1024]
    const float* W  = (const float*)d_in[1];  // [3, 1024]
    const float* b  = (const float*)d_in[2];  // [3]
    float*       out = (float*)d_out;         // [32, 2048, 3]

    // Derive the 5 dropout keys: jax.random.split(key(42), 5) with the
    // partitionable ("foldlike") scheme: child j = threefry((0,42), (0, j)).
    Keys kk;
    for (unsigned j = 0; j < 5; ++j) {
        tf_block_host(0u, 42u, 0u, j, &kk.k0[j], &kk.k1[j]);
    }

    const int rows = 32 * 2048;  // 65536
    nbme_head_kernel<<<rows, 256>>>(x, W, b, out, kk);
}